// round 1
// baseline (speedup 1.0000x reference)
#include <cuda_runtime.h>
#include <math.h>

#define T_FRAMES 16384
#define C        7
#define F_DIM    2048
#define LEN_Q    30
#define N_HEADS  4
#define D_K      64
#define D_FF     64

#define TA_FPB   16                      // frames per block, kernel A
#define TILE     64                      // frames per block, kernel B
#define ROWS     (TILE + LEN_Q - 1)      // 93 feature rows covered per tile
#define KSTR     260                     // padded row stride (floats) -> conflict-free

// scratch: per-frame spatial embedding feas = tanh(LF @ W_fc^T), (T, C)
__device__ float g_feas[T_FRAMES * C];

// ---------------------------------------------------------------------------
// Kernel A: feas[t][c] = tanh( sum_f LF[t][f] * W_fc[c][f] )
// W_fc held in registers (7 x 8 floats/thread), reused across TA_FPB frames.
// ---------------------------------------------------------------------------
__global__ __launch_bounds__(256) void feas_kernel(const float* __restrict__ LF,
                                                   const float* __restrict__ Wfc) {
    const int tid  = threadIdx.x;
    const int lane = tid & 31;
    const int warp = tid >> 5;
    const int t0   = blockIdx.x * TA_FPB;

    // each thread owns float4 chunks tid and tid+256 (512 float4 = 2048 floats)
    float4 w0[C], w1[C];
#pragma unroll
    for (int c = 0; c < C; ++c) {
        const float4* wf = reinterpret_cast<const float4*>(Wfc + c * F_DIM);
        w0[c] = wf[tid];
        w1[c] = wf[tid + 256];
    }

    __shared__ float red[8][C];

    for (int f = 0; f < TA_FPB; ++f) {
        const int t = t0 + f;
        const float4* lf = reinterpret_cast<const float4*>(LF + (size_t)t * F_DIM);
        const float4 a = lf[tid];
        const float4 b = lf[tid + 256];

        float p[C];
#pragma unroll
        for (int c = 0; c < C; ++c) {
            p[c] = a.x * w0[c].x + a.y * w0[c].y + a.z * w0[c].z + a.w * w0[c].w
                 + b.x * w1[c].x + b.y * w1[c].y + b.z * w1[c].z + b.w * w1[c].w;
        }
#pragma unroll
        for (int off = 16; off > 0; off >>= 1) {
#pragma unroll
            for (int c = 0; c < C; ++c)
                p[c] += __shfl_xor_sync(0xffffffffu, p[c], off);
        }
        if (lane == 0) {
#pragma unroll
            for (int c = 0; c < C; ++c) red[warp][c] = p[c];
        }
        __syncthreads();
        if (tid < C) {
            float s = 0.f;
#pragma unroll
            for (int wi = 0; wi < 8; ++wi) s += red[wi][tid];
            g_feas[t * C + tid] = tanhf(s);
        }
        __syncthreads();
    }
}

// ---------------------------------------------------------------------------
// Kernel B: per-tile fused  K/V projection + windowed MHA + LN1 + FFN + LN2.
// 256 threads = 64 frames x 4 heads. K/V in SMEM layout [row][d*4 + h],
// row stride 260 floats => bank = (4f + h + 4d) mod 32 is a lane permutation.
// ---------------------------------------------------------------------------
extern __shared__ float s_kv[];

__global__ __launch_bounds__(256, 1) void attn_kernel(
    const float* __restrict__ x,
    const float* __restrict__ Wq,  const float* __restrict__ Wk,
    const float* __restrict__ Wv,  const float* __restrict__ Wo,
    const float* __restrict__ ln1g, const float* __restrict__ ln1b,
    const float* __restrict__ Wff1, const float* __restrict__ Wff2,
    const float* __restrict__ ln2g, const float* __restrict__ ln2b,
    float* __restrict__ out)
{
    __shared__ float s_feats[ROWS][8];   // raw per-frame logits (window source)
    __shared__ float s_feas[TILE][8];    // spatial embedding (query source)

    float* Ks = s_kv;
    float* Vs = s_kv + ROWS * KSTR;

    const int tid = threadIdx.x;
    const int t0  = blockIdx.x * TILE;

    // load feature rows [t0-29, t0+63]; rows before frame 0 are zeros
    for (int i = tid; i < ROWS * C; i += 256) {
        const int r = i / C, c = i - r * C;
        const int g = t0 - (LEN_Q - 1) + r;
        s_feats[r][c] = (g >= 0) ? x[c * T_FRAMES + g] : 0.f;
    }
    for (int i = tid; i < TILE * C; i += 256) {
        const int r = i / C, c = i - r * C;
        s_feas[r][c] = g_feas[(t0 + r) * C + c];
    }
    __syncthreads();

    // project K, V once per row (bias-free => window gather is exact)
    for (int i = tid; i < ROWS * (N_HEADS * D_K); i += 256) {
        const int r = i >> 8;
        const int col = i & 255;
        const int h = col >> 6, d = col & 63;
        float sk = 0.f, sv = 0.f;
#pragma unroll
        for (int c = 0; c < C; ++c) {
            const float fv = s_feats[r][c];
            sk += fv * Wk[col * C + c];
            sv += fv * Wv[col * C + c];
        }
        Ks[r * KSTR + d * 4 + h] = sk;
        Vs[r * KSTR + d * 4 + h] = sv;
    }
    __syncthreads();

    const int f = tid >> 2;      // frame within tile
    const int h = tid & 3;       // head
    const int t = t0 + f;

    float ff[C];
#pragma unroll
    for (int c = 0; c < C; ++c) ff[c] = s_feas[f][c];

    // scores: d-outer / l-inner (only sc[30] is a register array)
    float sc[LEN_Q];
#pragma unroll
    for (int l = 0; l < LEN_Q; ++l) sc[l] = 0.f;

    const float* kbase = Ks + f * KSTR + h;
#pragma unroll 4
    for (int d = 0; d < D_K; ++d) {
        float qd = 0.f;
#pragma unroll
        for (int c = 0; c < C; ++c) qd += ff[c] * Wq[(h * D_K + d) * C + c];
        const float* kr = kbase + d * 4;
#pragma unroll
        for (int l = 0; l < LEN_Q; ++l) sc[l] += qd * kr[l * KSTR];
    }

    // softmax over 30 keys
    float mx = -1e30f;
#pragma unroll
    for (int l = 0; l < LEN_Q; ++l) { sc[l] *= 0.125f; mx = fmaxf(mx, sc[l]); }
    float den = 0.f;
#pragma unroll
    for (int l = 0; l < LEN_Q; ++l) { sc[l] = __expf(sc[l] - mx); den += sc[l]; }
    const float inv = 1.f / den;
#pragma unroll
    for (int l = 0; l < LEN_Q; ++l) sc[l] *= inv;

    // ctx and output projection partials (per head slice)
    float o[C];
#pragma unroll
    for (int c = 0; c < C; ++c) o[c] = 0.f;
    const float* vbase = Vs + f * KSTR + h;
#pragma unroll 4
    for (int d = 0; d < D_K; ++d) {
        const float* vr = vbase + d * 4;
        float s = 0.f;
#pragma unroll
        for (int l = 0; l < LEN_Q; ++l) s += sc[l] * vr[l * KSTR];
#pragma unroll
        for (int c = 0; c < C; ++c) o[c] += s * Wo[c * (N_HEADS * D_K) + h * D_K + d];
    }
    // reduce over the 4 head-lanes (xor-reduce: all lanes end with full sum)
#pragma unroll
    for (int c = 0; c < C; ++c) {
        o[c] += __shfl_xor_sync(0xffffffffu, o[c], 1);
        o[c] += __shfl_xor_sync(0xffffffffu, o[c], 2);
    }

    // LN1 (redundant on all 4 lanes so FFN can be split 4 ways)
    float res[C];
    float mu = 0.f;
#pragma unroll
    for (int c = 0; c < C; ++c) { res[c] = o[c] + ff[c]; mu += res[c]; }
    mu *= (1.f / C);
    float var = 0.f;
#pragma unroll
    for (int c = 0; c < C; ++c) { const float dv = res[c] - mu; var += dv * dv; }
    var *= (1.f / C);
    float rs = rsqrtf(var + 1e-5f);
#pragma unroll
    for (int c = 0; c < C; ++c) res[c] = (res[c] - mu) * rs * ln1g[c] + ln1b[c];

    // FFN: each lane handles 16 of 64 hidden units
    float y[C];
#pragma unroll
    for (int c = 0; c < C; ++c) y[c] = 0.f;
    const int j0 = h * 16;
#pragma unroll
    for (int jj = 0; jj < 16; ++jj) {
        const int j = j0 + jj;
        float a = 0.f;
#pragma unroll
        for (int c = 0; c < C; ++c) a += res[c] * Wff1[j * C + c];
        a = fmaxf(a, 0.f);
#pragma unroll
        for (int c = 0; c < C; ++c) y[c] += a * Wff2[c * D_FF + j];
    }
#pragma unroll
    for (int c = 0; c < C; ++c) {
        y[c] += __shfl_xor_sync(0xffffffffu, y[c], 1);
        y[c] += __shfl_xor_sync(0xffffffffu, y[c], 2);
    }

    if (h == 0) {
        float z[C];
        mu = 0.f;
#pragma unroll
        for (int c = 0; c < C; ++c) { z[c] = y[c] + res[c]; mu += z[c]; }
        mu *= (1.f / C);
        var = 0.f;
#pragma unroll
        for (int c = 0; c < C; ++c) { const float dv = z[c] - mu; var += dv * dv; }
        var *= (1.f / C);
        rs = rsqrtf(var + 1e-5f);
#pragma unroll
        for (int c = 0; c < C; ++c)
            out[t * C + c] = (z[c] - mu) * rs * ln2g[c] + ln2b[c];
    }
}

// ---------------------------------------------------------------------------
extern "C" void kernel_launch(void* const* d_in, const int* in_sizes, int n_in,
                              void* d_out, int out_size) {
    const float* x    = (const float*)d_in[0];
    const float* LF   = (const float*)d_in[1];
    const float* Wfc  = (const float*)d_in[2];
    const float* Wq   = (const float*)d_in[3];
    const float* Wk   = (const float*)d_in[4];
    const float* Wv   = (const float*)d_in[5];
    const float* Wo   = (const float*)d_in[6];
    const float* ln1g = (const float*)d_in[7];
    const float* ln1b = (const float*)d_in[8];
    const float* Wff1 = (const float*)d_in[9];
    const float* Wff2 = (const float*)d_in[10];
    const float* ln2g = (const float*)d_in[11];
    const float* ln2b = (const float*)d_in[12];
    float* out = (float*)d_out;

    const int smem_bytes = 2 * ROWS * KSTR * (int)sizeof(float);  // 193440
    cudaFuncSetAttribute(attn_kernel, cudaFuncAttributeMaxDynamicSharedMemorySize,
                         smem_bytes);

    feas_kernel<<<T_FRAMES / TA_FPB, 256>>>(LF, Wfc);
    attn_kernel<<<T_FRAMES / TILE, 256, smem_bytes>>>(
        x, Wq, Wk, Wv, Wo, ln1g, ln1b, Wff1, Wff2, ln2g, ln2b, out);
}

// round 2
// speedup vs baseline: 2.5213x; 2.5213x over previous
#include <cuda_runtime.h>
#include <math.h>

#define T_FRAMES 16384
#define C        7
#define F_DIM    2048
#define LEN_Q    30
#define N_HEADS  4
#define D_FF     64

#define TILE     64                   // frames per block
#define ROWS     (TILE + LEN_Q - 1)   // 93 feature rows per tile
#define NSTR     33                   // N/P row stride (words): bank = f+l+8h+c (perm)

// dynamic smem partition (floats):
//   red : TILE*32*8   = 16384   (feas warp-partials)
//   sN  : ROWS*NSTR   = 3069
//   sP  : ROWS*NSTR   = 3069
#define RED_F   (TILE * 32 * 8)
#define NP_F    (ROWS * NSTR)
#define DYN_F   (RED_F + 2 * NP_F)
#define DYN_B   (DYN_F * 4)

extern __shared__ float dyn[];

__global__ __launch_bounds__(256, 2) void fused_kernel(
    const float* __restrict__ x,    const float* __restrict__ LF,
    const float* __restrict__ Wfc,  const float* __restrict__ Wq,
    const float* __restrict__ Wk,   const float* __restrict__ Wv,
    const float* __restrict__ Wo,
    const float* __restrict__ ln1g, const float* __restrict__ ln1b,
    const float* __restrict__ Wff1, const float* __restrict__ Wff2,
    const float* __restrict__ ln2g, const float* __restrict__ ln2b,
    float* __restrict__ out)
{
    __shared__ float s_feats[ROWS][8];     // raw per-frame logits (key/value source)
    __shared__ float s_feas[TILE][8];      // tanh(FC(LF)) (query source)
    __shared__ float sA[N_HEADS][C][8];    // A_h = Wq_h^T Wk_h   (7x7 per head)
    __shared__ float sB[N_HEADS][C][8];    // B_h = Wo_h  Wv_h    (7x7 per head)

    float* red = dyn;
    float* sN  = dyn + RED_F;
    float* sP  = sN + NP_F;

    const int tid  = threadIdx.x;
    const int lane = tid & 31;
    const int warp = tid >> 5;
    const int t0   = blockIdx.x * TILE;

    // ---- phase 0: window feature rows from x (rows < 0 are zeros) ----
    for (int i = tid; i < ROWS * C; i += 256) {
        const int r = i / C, c = i - r * C;
        const int g = t0 - (LEN_Q - 1) + r;
        s_feats[r][c] = (g >= 0) ? x[c * T_FRAMES + g] : 0.f;
    }

    // ---- phase 1: feas = tanh(LF @ Wfc^T) for the 64 frames, block-cooperative
    //      W_fc in registers: thread owns float4 chunks tid and tid+256.
    {
        float4 w0[C], w1[C];
#pragma unroll
        for (int c = 0; c < C; ++c) {
            const float4* wf = reinterpret_cast<const float4*>(Wfc + c * F_DIM);
            w0[c] = wf[tid];
            w1[c] = wf[tid + 256];
        }
        const float4* lfb = reinterpret_cast<const float4*>(LF) + (size_t)t0 * 512;

        float4 a = lfb[tid];
        float4 b = lfb[tid + 256];
#pragma unroll 2
        for (int f = 0; f < TILE; ++f) {
            float4 an, bn;
            if (f < TILE - 1) {                      // prefetch next frame
                an = lfb[(f + 1) * 512 + tid];
                bn = lfb[(f + 1) * 512 + tid + 256];
            }
            float p[C];
#pragma unroll
            for (int c = 0; c < C; ++c) {
                p[c] = a.x * w0[c].x + a.y * w0[c].y + a.z * w0[c].z + a.w * w0[c].w
                     + b.x * w1[c].x + b.y * w1[c].y + b.z * w1[c].z + b.w * w1[c].w;
            }
            // 3 shuffle rounds -> lanes 0..3 hold the 4 group partials
#pragma unroll
            for (int off = 16; off >= 4; off >>= 1) {
#pragma unroll
                for (int c = 0; c < C; ++c)
                    p[c] += __shfl_xor_sync(0xffffffffu, p[c], off);
            }
            if (lane < 4) {
#pragma unroll
                for (int c = 0; c < C; ++c)
                    red[f * 256 + (warp * 4 + lane) * 8 + c] = p[c];
            }
            a = an; b = bn;
        }
    }

    // ---- phase 2: per-head 7x7 contractions A_h, B_h (196 threads) ----
    if (tid < N_HEADS * C * C) {
        const int h = tid / (C * C);
        const int rem = tid - h * (C * C);
        const int c = rem / C, c2 = rem - c * C;
        const float* wq = Wq + (h * 64) * C + c;     // stride C over d
        const float* wk = Wk + (h * 64) * C + c2;
        const float* wo = Wo + c * (N_HEADS * 64) + h * 64;  // stride 1 over d
        const float* wv = Wv + (h * 64) * C + c2;
        float sa = 0.f, sb = 0.f;
#pragma unroll 4
        for (int d = 0; d < 64; ++d) {
            sa = fmaf(wq[d * C], wk[d * C], sa);
            sb = fmaf(wo[d],     wv[d * C], sb);
        }
        sA[h][c][c2] = sa;
        sB[h][c][c2] = sb;
    }
    __syncthreads();

    // ---- phase 3a: finish feas reduction (8 warps x 4 partials) + tanh ----
    for (int i = tid; i < TILE * C; i += 256) {
        const int f = i / C, c = i - f * C;
        float s = 0.f;
#pragma unroll
        for (int j = 0; j < 32; ++j) {
            const int jj = (j + tid) & 31;           // stagger to spread banks
            s += red[f * 256 + jj * 8 + c];
        }
        s_feas[f][c] = tanhf(s);
    }

    // ---- phase 3b: N[r,h,c] = (A_h feat_r)[c],  P[r,h,c] = (B_h feat_r)[c] ----
    for (int i = tid; i < ROWS * N_HEADS * C; i += 256) {
        const int r = i / (N_HEADS * C);
        const int j = i - r * (N_HEADS * C);
        const int h = j / C, c = j - h * C;
        float sn = 0.f, sp = 0.f;
#pragma unroll
        for (int c2 = 0; c2 < C; ++c2) {
            const float fv = s_feats[r][c2];
            sn = fmaf(sA[h][c][c2], fv, sn);
            sp = fmaf(sB[h][c][c2], fv, sp);
        }
        sN[r * NSTR + h * 8 + c] = sn;
        sP[r * NSTR + h * 8 + c] = sp;
    }
    __syncthreads();

    // ---- phase 4: attention + LN1 + FFN + LN2 (thread = frame x head) ----
    const int f = tid >> 2;
    const int h = tid & 3;
    const int t = t0 + f;

    float ff[C];
#pragma unroll
    for (int c = 0; c < C; ++c) ff[c] = s_feas[f][c];

    // scores: sc[l] = (ff . N[f+l,h]) / 8
    float sc[LEN_Q];
    const float* nb = sN + f * NSTR + h * 8;
#pragma unroll
    for (int l = 0; l < LEN_Q; ++l) {
        const float* nr = nb + l * NSTR;
        float s = ff[0] * nr[0];
#pragma unroll
        for (int c = 1; c < C; ++c) s = fmaf(ff[c], nr[c], s);
        sc[l] = s * 0.125f;
    }

    // softmax over 30 keys
    float mx = sc[0];
#pragma unroll
    for (int l = 1; l < LEN_Q; ++l) mx = fmaxf(mx, sc[l]);
    float den = 0.f;
#pragma unroll
    for (int l = 0; l < LEN_Q; ++l) { sc[l] = __expf(sc[l] - mx); den += sc[l]; }
    const float inv = 1.f / den;
#pragma unroll
    for (int l = 0; l < LEN_Q; ++l) sc[l] *= inv;

    // o[c] = sum_l attn[l] * P[f+l,h,c]   (per-head slice)
    float o[C];
#pragma unroll
    for (int c = 0; c < C; ++c) o[c] = 0.f;
    const float* pb = sP + f * NSTR + h * 8;
#pragma unroll
    for (int l = 0; l < LEN_Q; ++l) {
        const float w = sc[l];
        const float* pr = pb + l * NSTR;
#pragma unroll
        for (int c = 0; c < C; ++c) o[c] = fmaf(w, pr[c], o[c]);
    }
    // reduce over 4 head-lanes
#pragma unroll
    for (int c = 0; c < C; ++c) {
        o[c] += __shfl_xor_sync(0xffffffffu, o[c], 1);
        o[c] += __shfl_xor_sync(0xffffffffu, o[c], 2);
    }

    // LN1 (all 4 lanes, so FFN splits 4 ways)
    float res[C];
    float mu = 0.f;
#pragma unroll
    for (int c = 0; c < C; ++c) { res[c] = o[c] + ff[c]; mu += res[c]; }
    mu *= (1.f / C);
    float var = 0.f;
#pragma unroll
    for (int c = 0; c < C; ++c) { const float dv = res[c] - mu; var += dv * dv; }
    var *= (1.f / C);
    float rs = rsqrtf(var + 1e-5f);
#pragma unroll
    for (int c = 0; c < C; ++c) res[c] = (res[c] - mu) * rs * ln1g[c] + ln1b[c];

    // FFN: each lane handles 16 of 64 hidden units
    float y[C];
#pragma unroll
    for (int c = 0; c < C; ++c) y[c] = 0.f;
    const int j0 = h * 16;
#pragma unroll
    for (int jj = 0; jj < 16; ++jj) {
        const int j = j0 + jj;
        float a = 0.f;
#pragma unroll
        for (int c = 0; c < C; ++c) a = fmaf(res[c], Wff1[j * C + c], a);
        a = fmaxf(a, 0.f);
#pragma unroll
        for (int c = 0; c < C; ++c) y[c] = fmaf(a, Wff2[c * D_FF + j], y[c]);
    }
#pragma unroll
    for (int c = 0; c < C; ++c) {
        y[c] += __shfl_xor_sync(0xffffffffu, y[c], 1);
        y[c] += __shfl_xor_sync(0xffffffffu, y[c], 2);
    }

    if (h == 0) {
        float z[C];
        mu = 0.f;
#pragma unroll
        for (int c = 0; c < C; ++c) { z[c] = y[c] + res[c]; mu += z[c]; }
        mu *= (1.f / C);
        var = 0.f;
#pragma unroll
        for (int c = 0; c < C; ++c) { const float dv = z[c] - mu; var += dv * dv; }
        var *= (1.f / C);
        rs = rsqrtf(var + 1e-5f);
#pragma unroll
        for (int c = 0; c < C; ++c)
            out[t * C + c] = (z[c] - mu) * rs * ln2g[c] + ln2b[c];
    }
}

// ---------------------------------------------------------------------------
extern "C" void kernel_launch(void* const* d_in, const int* in_sizes, int n_in,
                              void* d_out, int out_size) {
    const float* x    = (const float*)d_in[0];
    const float* LF   = (const float*)d_in[1];
    const float* Wfc  = (const float*)d_in[2];
    const float* Wq   = (const float*)d_in[3];
    const float* Wk   = (const float*)d_in[4];
    const float* Wv   = (const float*)d_in[5];
    const float* Wo   = (const float*)d_in[6];
    const float* ln1g = (const float*)d_in[7];
    const float* ln1b = (const float*)d_in[8];
    const float* Wff1 = (const float*)d_in[9];
    const float* Wff2 = (const float*)d_in[10];
    const float* ln2g = (const float*)d_in[11];
    const float* ln2b = (const float*)d_in[12];
    float* out = (float*)d_out;

    cudaFuncSetAttribute(fused_kernel,
                         cudaFuncAttributeMaxDynamicSharedMemorySize, DYN_B);
    fused_kernel<<<T_FRAMES / TILE, 256, DYN_B>>>(
        x, LF, Wfc, Wq, Wk, Wv, Wo, ln1g, ln1b,
        Wff1, Wff2, ln2g, ln2b, out);
}